// round 8
// baseline (speedup 1.0000x reference)
#include <cuda_runtime.h>

// CRF broadcast-add: out[b,l,i,j] = emission[b,l,j] + transition[i,j]
// B=32, L=512, T=64  ->  BL=16384 tiles, tile = 64x64 fp32 = 1024 float4
//
// Thread t (of 256) owns float4 positions p = t + 256k (k=0..3) in each tile.
// p%16 == t%16 -> one emission float4 per tile per thread; the 4 transition
// float4s are tile-invariant and live in registers.
//
// R8 single-variable change vs the 45.6us R3 kernel: default write-back
// stores instead of __stcs evict-first. Evidence: all store paths plateau at
// ~5.9 TB/s effective write rate (memory-system wall); stcs forces eager DRAM
// eviction and bursty write pressure, while default policy lets the 126 MB L2
// smooth the write stream.

constexpr int Bc = 32;
constexpr int Lc = 512;
constexpr int Tc = 64;
constexpr int BL = Bc * Lc;                 // 16384
constexpr int TILE_F4 = (Tc * Tc) / 4;      // 1024
constexpr int EM_F4_PER_TILE = Tc / 4;      // 16
constexpr int THREADS = 256;
constexpr int F4_PER_THREAD = TILE_F4 / THREADS;  // 4

__global__ void __launch_bounds__(THREADS, 8)
crf_broadcast_add(const float4* __restrict__ em4,
                  const float4* __restrict__ tr4,
                  float4* __restrict__ out4)
{
    const int t  = threadIdx.x;
    const int j4 = t & (EM_F4_PER_TILE - 1);   // t % 16

    // Tile-invariant transition rows -> registers, loaded once.
    float4 tr[F4_PER_THREAD];
#pragma unroll
    for (int k = 0; k < F4_PER_THREAD; ++k)
        tr[k] = __ldg(&tr4[t + THREADS * k]);

    for (int bl = blockIdx.x; bl < BL; bl += gridDim.x) {
        const float4 e = __ldg(&em4[(size_t)bl * EM_F4_PER_TILE + j4]);
        float4* __restrict__ o = out4 + (size_t)bl * TILE_F4;
#pragma unroll
        for (int k = 0; k < F4_PER_THREAD; ++k) {
            float4 v;
            v.x = e.x + tr[k].x;
            v.y = e.y + tr[k].y;
            v.z = e.z + tr[k].z;
            v.w = e.w + tr[k].w;
            o[t + THREADS * k] = v;        // default write-back (no .cs hint)
        }
    }
}

extern "C" void kernel_launch(void* const* d_in, const int* in_sizes, int n_in,
                              void* d_out, int out_size)
{
    const float4* em4 = (const float4*)d_in[0];   // emission [B, L, T] fp32
    const float4* tr4 = (const float4*)d_in[1];   // transition [T, T] fp32
    float4* out4      = (float4*)d_out;           // [B, L, T, T] fp32

    const int grid = 152 * 8;   // GB300: 152 SMs, 8 CTAs/SM resident
    crf_broadcast_add<<<grid, THREADS>>>(em4, tr4, out4);
}

// round 9
// speedup vs baseline: 1.0063x; 1.0063x over previous
#include <cuda_runtime.h>

// CRF broadcast-add: out[b,l,i,j] = emission[b,l,j] + transition[i,j]
// B=32, L=512, T=64  ->  BL=16384 tiles, tile = 64x64 fp32 = 1024 float4
//
// Thread t (of 256) owns float4 positions p = t + 256k (k=0..3) in each tile.
// p%16 == t%16 -> one emission float4 per tile per thread; the 4 transition
// float4s are tile-invariant and live in registers.
//
// R9 single-variable change vs R3 (45.6us, stcs): write-THROUGH stores
// (__stwt). Evidence from R8: write-back won the isolated ncu launch (43.8us)
// but lost the harness steady state (51.3us) because dirty L2 residue drains
// into the next graph replay. Harness metric = kernel + residue drain.
// Write-through leaves zero dirty residue and no L2 pollution.

constexpr int Bc = 32;
constexpr int Lc = 512;
constexpr int Tc = 64;
constexpr int BL = Bc * Lc;                 // 16384
constexpr int TILE_F4 = (Tc * Tc) / 4;      // 1024
constexpr int EM_F4_PER_TILE = Tc / 4;      // 16
constexpr int THREADS = 256;
constexpr int F4_PER_THREAD = TILE_F4 / THREADS;  // 4

__global__ void __launch_bounds__(THREADS, 8)
crf_broadcast_add(const float4* __restrict__ em4,
                  const float4* __restrict__ tr4,
                  float4* __restrict__ out4)
{
    const int t  = threadIdx.x;
    const int j4 = t & (EM_F4_PER_TILE - 1);   // t % 16

    // Tile-invariant transition rows -> registers, loaded once.
    float4 tr[F4_PER_THREAD];
#pragma unroll
    for (int k = 0; k < F4_PER_THREAD; ++k)
        tr[k] = __ldg(&tr4[t + THREADS * k]);

    for (int bl = blockIdx.x; bl < BL; bl += gridDim.x) {
        const float4 e = __ldg(&em4[(size_t)bl * EM_F4_PER_TILE + j4]);
        float4* __restrict__ o = out4 + (size_t)bl * TILE_F4;
#pragma unroll
        for (int k = 0; k < F4_PER_THREAD; ++k) {
            float4 v;
            v.x = e.x + tr[k].x;
            v.y = e.y + tr[k].y;
            v.z = e.z + tr[k].z;
            v.w = e.w + tr[k].w;
            __stwt(&o[t + THREADS * k], v);   // write-through: no dirty L2 residue
        }
    }
}

extern "C" void kernel_launch(void* const* d_in, const int* in_sizes, int n_in,
                              void* d_out, int out_size)
{
    const float4* em4 = (const float4*)d_in[0];   // emission [B, L, T] fp32
    const float4* tr4 = (const float4*)d_in[1];   // transition [T, T] fp32
    float4* out4      = (float4*)d_out;           // [B, L, T, T] fp32

    const int grid = 152 * 8;   // GB300: 152 SMs, 8 CTAs/SM resident
    crf_broadcast_add<<<grid, THREADS>>>(em4, tr4, out4);
}

// round 12
// speedup vs baseline: 1.0905x; 1.0837x over previous
#include <cuda_runtime.h>

// CRF broadcast-add: out[b,l,i,j] = emission[b,l,j] + transition[i,j]
// B=32, L=512, T=64  ->  BL=16384 tiles, tile = 64x64 fp32 = 1024 float4
//
// Winning recipe (R3): thread t of 256 owns float4 positions t+256k per tile;
// transition float4s are tile-invariant -> registers; __stcs evict-first
// stores (best of stcs/writeback/stwt/TMA/prefetch across R3-R9).
//
// R10 change: 2 adjacent tiles per grid-stride iteration -> 32KB contiguous
// store burst per CTA iteration (better DRAM row locality), 8 STG.128s of
// store ILP per thread, half the loop overhead.

constexpr int Bc = 32;
constexpr int Lc = 512;
constexpr int Tc = 64;
constexpr int BL = Bc * Lc;                 // 16384 tiles
constexpr int NPAIR = BL / 2;               // 8192 tile-pairs
constexpr int TILE_F4 = (Tc * Tc) / 4;      // 1024
constexpr int EM_F4_PER_TILE = Tc / 4;      // 16
constexpr int THREADS = 256;
constexpr int F4_PER_THREAD = TILE_F4 / THREADS;  // 4

__global__ void __launch_bounds__(THREADS, 8)
crf_broadcast_add(const float4* __restrict__ em4,
                  const float4* __restrict__ tr4,
                  float4* __restrict__ out4)
{
    const int t  = threadIdx.x;
    const int j4 = t & (EM_F4_PER_TILE - 1);   // t % 16

    // Tile-invariant transition rows -> registers, loaded once.
    float4 tr[F4_PER_THREAD];
#pragma unroll
    for (int k = 0; k < F4_PER_THREAD; ++k)
        tr[k] = __ldg(&tr4[t + THREADS * k]);

    for (int p = blockIdx.x; p < NPAIR; p += gridDim.x) {
        const int bl = p * 2;                   // two adjacent tiles
        const float4 e0 = __ldg(&em4[(size_t)bl * EM_F4_PER_TILE + j4]);
        const float4 e1 = __ldg(&em4[(size_t)(bl + 1) * EM_F4_PER_TILE + j4]);
        float4* __restrict__ o = out4 + (size_t)bl * TILE_F4;
#pragma unroll
        for (int k = 0; k < F4_PER_THREAD; ++k) {
            float4 v;
            v.x = e0.x + tr[k].x;
            v.y = e0.y + tr[k].y;
            v.z = e0.z + tr[k].z;
            v.w = e0.w + tr[k].w;
            __stcs(&o[t + THREADS * k], v);
        }
#pragma unroll
        for (int k = 0; k < F4_PER_THREAD; ++k) {
            float4 v;
            v.x = e1.x + tr[k].x;
            v.y = e1.y + tr[k].y;
            v.z = e1.z + tr[k].z;
            v.w = e1.w + tr[k].w;
            __stcs(&o[TILE_F4 + t + THREADS * k], v);
        }
    }
}

extern "C" void kernel_launch(void* const* d_in, const int* in_sizes, int n_in,
                              void* d_out, int out_size)
{
    const float4* em4 = (const float4*)d_in[0];   // emission [B, L, T] fp32
    const float4* tr4 = (const float4*)d_in[1];   // transition [T, T] fp32
    float4* out4      = (float4*)d_out;           // [B, L, T, T] fp32

    const int grid = 152 * 8;   // GB300: 152 SMs, 8 CTAs/SM resident
    crf_broadcast_add<<<grid, THREADS>>>(em4, tr4, out4);
}

// round 14
// speedup vs baseline: 1.1094x; 1.0173x over previous
#include <cuda_runtime.h>

// CRF broadcast-add: out[b,l,i,j] = emission[b,l,j] + transition[i,j]
// B=32, L=512, T=64  ->  BL=16384 tiles, tile = 64x64 fp32 = 1024 float4
//
// FINAL (= R3, the measured optimum at 45.6us harness):
//  - thread t of 256 owns float4 positions t+256k (k=0..3) per tile;
//    p%16 == t%16 -> one emission float4 per tile per thread
//  - 4 transition float4s are tile-invariant -> registers, loaded once
//  - __stcs evict-first stores: best of {stcs, writeback, stwt, TMA bulk}
//    in graph-replay steady state (dirty-L2 residue drains into the next
//    replay for write-back; .wt and TMA paths are slower sustained)
//  - flat grid-stride, 16384 work units: best granularity of {1-tile, 2-tile}
//
// Measured matrix (harness us): R3 45.6 | pair 47.0 | prefetch 47.6 |
// TMA 50.3 | stwt 50.9 | writeback 51.3. Memory-system bound (~5.9 TB/s
// effective write stream); no SM-side resource saturated.

constexpr int Bc = 32;
constexpr int Lc = 512;
constexpr int Tc = 64;
constexpr int BL = Bc * Lc;                 // 16384
constexpr int TILE_F4 = (Tc * Tc) / 4;      // 1024
constexpr int EM_F4_PER_TILE = Tc / 4;      // 16
constexpr int THREADS = 256;
constexpr int F4_PER_THREAD = TILE_F4 / THREADS;  // 4

__global__ void __launch_bounds__(THREADS, 8)
crf_broadcast_add(const float4* __restrict__ em4,
                  const float4* __restrict__ tr4,
                  float4* __restrict__ out4)
{
    const int t  = threadIdx.x;
    const int j4 = t & (EM_F4_PER_TILE - 1);   // t % 16

    // Tile-invariant transition rows -> registers, loaded once.
    float4 tr[F4_PER_THREAD];
#pragma unroll
    for (int k = 0; k < F4_PER_THREAD; ++k)
        tr[k] = __ldg(&tr4[t + THREADS * k]);

    for (int bl = blockIdx.x; bl < BL; bl += gridDim.x) {
        const float4 e = __ldg(&em4[(size_t)bl * EM_F4_PER_TILE + j4]);
        float4* __restrict__ o = out4 + (size_t)bl * TILE_F4;
#pragma unroll
        for (int k = 0; k < F4_PER_THREAD; ++k) {
            float4 v;
            v.x = e.x + tr[k].x;
            v.y = e.y + tr[k].y;
            v.z = e.z + tr[k].z;
            v.w = e.w + tr[k].w;
            __stcs(&o[t + THREADS * k], v);   // streaming: evict-first
        }
    }
}

extern "C" void kernel_launch(void* const* d_in, const int* in_sizes, int n_in,
                              void* d_out, int out_size)
{
    const float4* em4 = (const float4*)d_in[0];   // emission [B, L, T] fp32
    const float4* tr4 = (const float4*)d_in[1];   // transition [T, T] fp32
    float4* out4      = (float4*)d_out;           // [B, L, T, T] fp32

    const int grid = 152 * 8;   // GB300: 152 SMs, 8 CTAs/SM resident
    crf_broadcast_add<<<grid, THREADS>>>(em4, tr4, out4);
}

// round 15
// speedup vs baseline: 1.2806x; 1.1543x over previous
#include <cuda_runtime.h>

// CRF broadcast-add: out[b,l,i,j] = emission[b,l,j] + transition[i,j]
// B=32, L=512, T=64  ->  BL=16384 tiles, tile = 64x64 fp32 = 1024 float4
//
// Recipe (validated R3..R14):
//  - thread t of 256 owns float4 positions t+256k (k=0..3) per tile;
//    p%16 == t%16 -> one emission float4 per tile per thread
//  - 4 transition float4s per thread: tile-invariant, L2-resident loads
//  - __stcs evict-first stores: best of {stcs, writeback, stwt, TMA bulk}
//    in graph-replay steady state
//
// R15 change (last untested axis = work distribution): one tile per CTA,
// grid = 16384, no software grid-stride. The HW work distributor balances
// tiles across SMs with no tail quantization; the 1216-CTA grid-stride
// version gave 14 tiles to some CTAs and 13 to others (~3.7% exposed tail).

constexpr int Tc = 64;
constexpr int BL = 32 * 512;                // 16384 tiles
constexpr int TILE_F4 = (Tc * Tc) / 4;      // 1024
constexpr int EM_F4_PER_TILE = Tc / 4;      // 16
constexpr int THREADS = 256;
constexpr int F4_PER_THREAD = TILE_F4 / THREADS;  // 4

__global__ void __launch_bounds__(THREADS, 8)
crf_broadcast_add(const float4* __restrict__ em4,
                  const float4* __restrict__ tr4,
                  float4* __restrict__ out4)
{
    const int t  = threadIdx.x;
    const int bl = blockIdx.x;                 // one tile per CTA
    const int j4 = t & (EM_F4_PER_TILE - 1);   // t % 16

    // Emission float4 for this tile (L2/DRAM) and the thread's 4 transition
    // float4s (L2-resident after first wave) issued back-to-back.
    const float4 e = __ldg(&em4[(size_t)bl * EM_F4_PER_TILE + j4]);

    float4 tr[F4_PER_THREAD];
#pragma unroll
    for (int k = 0; k < F4_PER_THREAD; ++k)
        tr[k] = __ldg(&tr4[t + THREADS * k]);

    float4* __restrict__ o = out4 + (size_t)bl * TILE_F4;
#pragma unroll
    for (int k = 0; k < F4_PER_THREAD; ++k) {
        float4 v;
        v.x = e.x + tr[k].x;
        v.y = e.y + tr[k].y;
        v.z = e.z + tr[k].z;
        v.w = e.w + tr[k].w;
        __stcs(&o[t + THREADS * k], v);        // streaming: evict-first
    }
}

extern "C" void kernel_launch(void* const* d_in, const int* in_sizes, int n_in,
                              void* d_out, int out_size)
{
    const float4* em4 = (const float4*)d_in[0];   // emission [B, L, T] fp32
    const float4* tr4 = (const float4*)d_in[1];   // transition [T, T] fp32
    float4* out4      = (float4*)d_out;           // [B, L, T, T] fp32

    crf_broadcast_add<<<BL, THREADS>>>(em4, tr4, out4);  // one tile per CTA
}